// round 15
// baseline (speedup 1.0000x reference)
#include <cuda_runtime.h>
#include <cuda_fp16.h>
#include <math.h>
#include <stdint.h>

#define NTOK 2048
#define CDIM 768
#define HDIM 3072
#define NE   8

// ---------------- scratch ----------------
__device__ __align__(1024) __half g_xg[NE * NTOK * CDIM];
__device__ __align__(1024) __half g_wfc[NE * HDIM * CDIM];
__device__ __align__(1024) __half g_wp[NE * CDIM * HDIM];
__device__ __align__(1024) __half g_h[(size_t)NE * NTOK * HDIM];
__device__ int   g_cnt[NE];
__device__ int   g_tok[NE * NTOK];
__device__ float g_p[NE * NTOK];

// ---------------- helpers ----------------
__device__ __forceinline__ uint32_t smem_u32(const void* p) {
    uint32_t a;
    asm("{ .reg .u64 t; cvta.to.shared.u64 t, %1; cvt.u32.u64 %0, t; }" : "=r"(a) : "l"(p));
    return a;
}
__device__ __forceinline__ void cpa16(uint32_t dst, const void* src) {
    asm volatile("cp.async.cg.shared.global [%0], [%1], 16;" :: "r"(dst), "l"(src));
}
#define CP_COMMIT() asm volatile("cp.async.commit_group;" ::: "memory")
#define CP_WAIT(n)  asm volatile("cp.async.wait_group %0;" :: "n"(n) : "memory")

__device__ __forceinline__ void ldsm4(uint32_t* r, uint32_t addr) {
    asm volatile("ldmatrix.sync.aligned.m8n8.x4.shared.b16 {%0,%1,%2,%3}, [%4];"
        : "=r"(r[0]), "=r"(r[1]), "=r"(r[2]), "=r"(r[3]) : "r"(addr));
}
__device__ __forceinline__ void mma16816(float* d, const uint32_t* a,
                                         uint32_t b0, uint32_t b1) {
    asm volatile("mma.sync.aligned.m16n8k16.row.col.f32.f16.f16.f32 "
        "{%0,%1,%2,%3}, {%4,%5,%6,%7}, {%8,%9}, {%0,%1,%2,%3};"
        : "+f"(d[0]), "+f"(d[1]), "+f"(d[2]), "+f"(d[3])
        : "r"(a[0]), "r"(a[1]), "r"(a[2]), "r"(a[3]), "r"(b0), "r"(b1));
}
__device__ __forceinline__ float gelu_tanh(float v) {
    float c = 0.7978845608028654f;
    return 0.5f * v * (1.0f + tanhf(c * (v + 0.044715f * v * v * v)));
}

// ---------------- tiny kernels ----------------
__global__ void clear_cnt_kernel() {
    if (threadIdx.x < NE) g_cnt[threadIdx.x] = 0;
}
__global__ void zero_out_kernel(float4* out, int n4) {
    int i = blockIdx.x * blockDim.x + threadIdx.x;
    float4 z = make_float4(0.f, 0.f, 0.f, 0.f);
    for (; i < n4; i += gridDim.x * blockDim.x) out[i] = z;
}

// ---------------- kernel: router ----------------
__global__ void router_kernel(const float* __restrict__ x, const float* __restrict__ wg) {
    int warp = (blockIdx.x * blockDim.x + threadIdx.x) >> 5;
    int lane = threadIdx.x & 31;
    if (warp >= NTOK) return;
    const float4* xr = (const float4*)(x + (size_t)warp * CDIM);

    float4 v[6];
#pragma unroll
    for (int i = 0; i < 6; i++) v[i] = xr[lane + 32 * i];

    float acc[NE];
#pragma unroll
    for (int e = 0; e < NE; e++) acc[e] = 0.0f;
#pragma unroll
    for (int i = 0; i < 6; i++) {
        int c0 = (lane + 32 * i) * 4;
        float vv[4] = {v[i].x, v[i].y, v[i].z, v[i].w};
#pragma unroll
        for (int q = 0; q < 4; q++) {
            const float4* w4 = (const float4*)(wg + (size_t)(c0 + q) * NE);
            float4 a = w4[0], b = w4[1];
            float xv = vv[q];
            acc[0] += xv * a.x; acc[1] += xv * a.y; acc[2] += xv * a.z; acc[3] += xv * a.w;
            acc[4] += xv * b.x; acc[5] += xv * b.y; acc[6] += xv * b.z; acc[7] += xv * b.w;
        }
    }
#pragma unroll
    for (int e = 0; e < NE; e++)
        for (int off = 16; off; off >>= 1)
            acc[e] += __shfl_xor_sync(0xffffffffu, acc[e], off);
    if (lane == 0) {
        int i0 = 0; float l0 = acc[0];
        for (int e = 1; e < NE; e++) if (acc[e] > l0) { l0 = acc[e]; i0 = e; }
        int i1 = -1; float l1 = -1e30f;
        for (int e = 0; e < NE; e++) if (e != i0 && acc[e] > l1) { l1 = acc[e]; i1 = e; }
        float r  = expf(l1 - l0);
        float p0 = 1.0f / (1.0f + r);
        float p1 = r / (1.0f + r);
        int pos0 = atomicAdd(&g_cnt[i0], 1);
        g_tok[i0 * NTOK + pos0] = warp; g_p[i0 * NTOK + pos0] = p0;
        int pos1 = atomicAdd(&g_cnt[i1], 1);
        g_tok[i1 * NTOK + pos1] = warp; g_p[i1 * NTOK + pos1] = p1;
    }
}

// ---------------- kernel: gather x ----------------
__global__ __launch_bounds__(256) void gather_x(const float* __restrict__ x) {
    int g = blockIdx.x * 8 + (threadIdx.x >> 5);
    int lane = threadIdx.x & 31;
    int e = g >> 11, row = g & 2047;
    int cnt = g_cnt[e];
    size_t dst = (size_t)g * CDIM;
    if (row >= cnt) {
        if (row < ((cnt + 127) & ~127)) {
            uint4 z = make_uint4(0, 0, 0, 0);
            for (int c = lane * 8; c < CDIM; c += 256)
                *(uint4*)(g_xg + dst + c) = z;
        }
        return;
    }
    int tok = g_tok[g];
    const float4* xr = (const float4*)(x + (size_t)tok * CDIM);
#pragma unroll
    for (int i = 0; i < 6; i++) {
        float4 v = xr[lane + 32 * i];
        __half2 h0 = __floats2half2_rn(v.x, v.y);
        __half2 h1 = __floats2half2_rn(v.z, v.w);
        uint2 pk = make_uint2(*(uint32_t*)&h0, *(uint32_t*)&h1);
        *(uint2*)(g_xg + dst + (lane + 32 * i) * 4) = pk;
    }
}

// ---------------- kernel: repack weights ----------------
// src[(k*NT + n)*8 + e] -> dst[(e*NT + n)*KT + k]
__global__ __launch_bounds__(256) void repack_w(const float* __restrict__ src,
                                                __half* __restrict__ dst,
                                                int KT, int NT, int yoff) {
    __shared__ __align__(16) unsigned short st[8][264];
    int n  = blockIdx.y + yoff;
    int k0 = blockIdx.x * 256;
    int t  = threadIdx.x;
    int k  = k0 + t;
    const float4* s4 = (const float4*)(src + ((size_t)k * NT + n) * 8);
    float4 a = s4[0], b = s4[1];
    float v[8] = {a.x, a.y, a.z, a.w, b.x, b.y, b.z, b.w};
#pragma unroll
    for (int e = 0; e < 8; e++)
        st[e][t] = __half_as_ushort(__float2half(v[e]));
    __syncthreads();
    int p = t >> 5, i = t & 31;
    size_t off = ((size_t)p * NT + n) * KT + k0 + i * 8;
    *(uint4*)(dst + off) = *(const uint4*)&st[p][i * 8];
}

// ---------------- tensor-core GEMM (fp16, R11 core, NST=3, BK=32) ----------
// PHASE 1: D = Xg @ Wfc^T, gelu -> g_h             (WM=2 -> BM=64)
// PHASE 2: D = H  @ Wp^T,  * p -> atomicAdd(out)   (WM=2 -> BM=64)
template <int WM, int PHASE>
__global__ __launch_bounds__(256) void gemm_ws(
    const __half* __restrict__ A, const __half* __restrict__ B,
    int Kdim, int Ndim, float* __restrict__ out) {

    constexpr int BM  = WM * 32;
    constexpr int BN  = 128;
    constexpr int BK  = 32;
    constexpr int SA  = BK + 8;
    constexpr int NST = 3;
    constexpr int ASZ = BM * SA;
    constexpr int BSZ = BN * SA;
    constexpr int STG = ASZ + BSZ;

    int e   = blockIdx.z;
    int cnt = g_cnt[e];
    int m0  = blockIdx.x * BM;
    if (m0 >= cnt) return;
    int n0  = blockIdx.y * BN;

    extern __shared__ __half sm[];
    uint32_t sbase = smem_u32(sm);

    const __half* A_p = A + ((size_t)e * NTOK + m0) * Kdim;
    const __half* B_p = B + ((size_t)e * Ndim + n0) * Kdim;

    int tid  = threadIdx.x;
    int lane = tid & 31;
    int wid  = tid >> 5;
    int wm   = wid & 1;
    int wn   = wid >> 1;
    int mb   = wm * WM * 16;
    int nb   = wn * 32;

    auto issue = [&](int stage, int kb) {
        int k0 = kb * BK;
        uint32_t s0 = sbase + stage * STG * 2;
#pragma unroll
        for (int t = tid; t < BM * 4; t += 256) {
            int r = t >> 2, c = t & 3;
            cpa16(s0 + (r * SA + c * 8) * 2, A_p + (size_t)r * Kdim + k0 + c * 8);
        }
#pragma unroll
        for (int t = tid; t < BN * 4; t += 256) {
            int r = t >> 2, c = t & 3;
            cpa16(s0 + (ASZ + r * SA + c * 8) * 2, B_p + (size_t)r * Kdim + k0 + c * 8);
        }
        CP_COMMIT();
    };

    float acc[WM][4][4];
#pragma unroll
    for (int i = 0; i < WM; i++)
#pragma unroll
        for (int j = 0; j < 4; j++)
#pragma unroll
            for (int q = 0; q < 4; q++) acc[i][j][q] = 0.0f;

    int q8   = lane >> 3;
    int rr   = lane & 7;
    int lrow = rr + (q8 & 1) * 8;
    int lcol = (q8 >> 1) * 8;

    auto compute = [&](int stage) {
        uint32_t s0 = sbase + stage * STG * 2;
#pragma unroll
        for (int kk = 0; kk < BK; kk += 16) {
            uint32_t a[WM][4];
#pragma unroll
            for (int mi = 0; mi < WM; mi++)
                ldsm4(a[mi], s0 + ((mb + mi * 16 + lrow) * SA + kk + lcol) * 2);
#pragma unroll
            for (int np = 0; np < 2; np++) {
                uint32_t b[4];
                ldsm4(b, s0 + (ASZ + (nb + np * 16 + lrow) * SA + kk + lcol) * 2);
#pragma unroll
                for (int s = 0; s < 2; s++)
#pragma unroll
                    for (int mi = 0; mi < WM; mi++)
                        mma16816(acc[mi][np * 2 + s], a[mi], b[s], b[s + 2]);
            }
        }
    };

    int KIT = Kdim / BK;
#pragma unroll
    for (int s = 0; s < NST - 1; s++) issue(s, s);
#pragma unroll 1
    for (int it = 0; it < KIT; it++) {
        CP_WAIT(NST - 2);
        __syncthreads();
        int nk = it + NST - 1;
        if (nk < KIT) issue(nk % NST, nk);
        compute(it % NST);
    }

    // ---------------- epilogue ----------------
    int fr = lane >> 2;
    int fc = (lane & 3) * 2;

    if (PHASE == 1) {
#pragma unroll
        for (int mi = 0; mi < WM; mi++) {
#pragma unroll
            for (int half = 0; half < 2; half++) {
                int r = m0 + mb + mi * 16 + fr + half * 8;
                size_t base = ((size_t)e * NTOK + r) * HDIM;
#pragma unroll
                for (int ni = 0; ni < 4; ni++) {
                    int cg = n0 + nb + ni * 8 + fc;
                    float v0 = gelu_tanh(acc[mi][ni][half * 2 + 0]);
                    float v1 = gelu_tanh(acc[mi][ni][half * 2 + 1]);
                    uint32_t pk = (uint32_t)__half_as_ushort(__float2half(v0)) |
                                  ((uint32_t)__half_as_ushort(__float2half(v1)) << 16);
                    *(uint32_t*)(g_h + base + cg) = pk;
                }
            }
        }
    } else {
#pragma unroll
        for (int mi = 0; mi < WM; mi++) {
#pragma unroll
            for (int half = 0; half < 2; half++) {
                int slot = m0 + mb + mi * 16 + fr + half * 8;
                if (slot < cnt) {
                    int   tok = g_tok[e * NTOK + slot];
                    float pw  = g_p[e * NTOK + slot];
                    float* orow = out + (size_t)tok * CDIM;
#pragma unroll
                    for (int ni = 0; ni < 4; ni++) {
                        int cg = n0 + nb + ni * 8 + fc;
                        atomicAdd(orow + cg,     pw * acc[mi][ni][half * 2 + 0]);
                        atomicAdd(orow + cg + 1, pw * acc[mi][ni][half * 2 + 1]);
                    }
                }
            }
        }
    }
}

// ---------------- host ----------------
extern "C" void kernel_launch(void* const* d_in, const int* in_sizes, int n_in,
                              void* d_out, int out_size) {
    const float* x      = (const float*)d_in[0];
    const float* w_fc   = (const float*)d_in[1];
    const float* w_proj = (const float*)d_in[2];
    const float* w_gate = (const float*)d_in[3];
    float* out = (float*)d_out;

    void *p_f, *p_p, *p_x, *p_h;
    cudaGetSymbolAddress(&p_f, g_wfc);
    cudaGetSymbolAddress(&p_p, g_wp);
    cudaGetSymbolAddress(&p_x, g_xg);
    cudaGetSymbolAddress(&p_h, g_h);

    constexpr int SMEM1 = 3 * (64 * 40 + 128 * 40) * 2;   // 46080 (BM=64)
    constexpr int SMEM2 = 3 * (64 * 40 + 128 * 40) * 2;   // 46080

    static cudaStream_t s2 = nullptr, s3 = nullptr;
    static cudaEvent_t ev0, ev_fc0, ev_fc1, ev_pj, ev_z;
    if (!s2) {
        cudaStreamCreateWithFlags(&s2, cudaStreamNonBlocking);
        cudaStreamCreateWithFlags(&s3, cudaStreamNonBlocking);
        cudaEventCreateWithFlags(&ev0,   cudaEventDisableTiming);
        cudaEventCreateWithFlags(&ev_fc0, cudaEventDisableTiming);
        cudaEventCreateWithFlags(&ev_fc1, cudaEventDisableTiming);
        cudaEventCreateWithFlags(&ev_pj,  cudaEventDisableTiming);
        cudaEventCreateWithFlags(&ev_z,   cudaEventDisableTiming);
        cudaFuncSetAttribute(gemm_ws<2, 1>, cudaFuncAttributeMaxDynamicSharedMemorySize, SMEM1);
        cudaFuncSetAttribute(gemm_ws<2, 2>, cudaFuncAttributeMaxDynamicSharedMemorySize, SMEM2);
    }

    // fork
    cudaEventRecord(ev0, 0);
    cudaStreamWaitEvent(s2, ev0, 0);
    cudaStreamWaitEvent(s3, ev0, 0);

    // s2: repack_fc half 0, then repack_proj (hidden under gemm1)
    repack_w<<<dim3(CDIM / 256, HDIM / 2), 256, 0, s2>>>(w_fc, (__half*)p_f, CDIM, HDIM, 0);
    cudaEventRecord(ev_fc0, s2);
    // s3: repack_fc half 1, then zero_out
    repack_w<<<dim3(CDIM / 256, HDIM / 2), 256, 0, s3>>>(w_fc, (__half*)p_f, CDIM, HDIM, HDIM / 2);
    cudaEventRecord(ev_fc1, s3);

    repack_w<<<dim3(HDIM / 256, CDIM), 256, 0, s2>>>(w_proj, (__half*)p_p, HDIM, CDIM, 0);
    cudaEventRecord(ev_pj, s2);
    zero_out_kernel<<<256, 256, 0, s3>>>((float4*)out, NTOK * CDIM / 4);
    cudaEventRecord(ev_z, s3);

    // main: token path
    clear_cnt_kernel<<<1, 32>>>();
    router_kernel<<<NTOK / 8, 256>>>(x, w_gate);
    gather_x<<<NE * NTOK / 8, 256>>>(x);

    cudaStreamWaitEvent(0, ev_fc0, 0);
    cudaStreamWaitEvent(0, ev_fc1, 0);
    dim3 g1(NTOK / 64, HDIM / 128, NE);   // (32, 24, 8)
    gemm_ws<2, 1><<<g1, 256, SMEM1>>>((const __half*)p_x, (const __half*)p_f,
                                      CDIM, HDIM, out);
    cudaStreamWaitEvent(0, ev_pj, 0);
    cudaStreamWaitEvent(0, ev_z, 0);
    dim3 g2(NTOK / 64, CDIM / 128, NE);   // (32, 6, 8)
    gemm_ws<2, 2><<<g2, 256, SMEM2>>>((const __half*)p_h, (const __half*)p_p,
                                      HDIM, CDIM, out);
}

// round 16
// speedup vs baseline: 1.5359x; 1.5359x over previous
#include <cuda_runtime.h>
#include <cuda_fp16.h>
#include <math.h>
#include <stdint.h>

#define NTOK 2048
#define CDIM 768
#define HDIM 3072
#define NE   8

// ---------------- scratch ----------------
__device__ __align__(1024) __half g_xg[NE * NTOK * CDIM];
__device__ __align__(1024) __half g_wfc[NE * HDIM * CDIM];
__device__ __align__(1024) __half g_wp[NE * CDIM * HDIM];
__device__ __align__(1024) __half g_h[(size_t)NE * NTOK * HDIM];
__device__ int   g_cnt[NE];
__device__ int   g_tok[NE * NTOK];
__device__ float g_p[NE * NTOK];

// ---------------- helpers ----------------
__device__ __forceinline__ uint32_t smem_u32(const void* p) {
    uint32_t a;
    asm("{ .reg .u64 t; cvta.to.shared.u64 t, %1; cvt.u32.u64 %0, t; }" : "=r"(a) : "l"(p));
    return a;
}
__device__ __forceinline__ void cpa16(uint32_t dst, const void* src) {
    asm volatile("cp.async.cg.shared.global [%0], [%1], 16;" :: "r"(dst), "l"(src));
}
#define CP_COMMIT() asm volatile("cp.async.commit_group;" ::: "memory")
#define CP_WAIT(n)  asm volatile("cp.async.wait_group %0;" :: "n"(n) : "memory")

__device__ __forceinline__ void ldsm4(uint32_t* r, uint32_t addr) {
    asm volatile("ldmatrix.sync.aligned.m8n8.x4.shared.b16 {%0,%1,%2,%3}, [%4];"
        : "=r"(r[0]), "=r"(r[1]), "=r"(r[2]), "=r"(r[3]) : "r"(addr));
}
__device__ __forceinline__ void mma16816(float* d, const uint32_t* a,
                                         uint32_t b0, uint32_t b1) {
    asm volatile("mma.sync.aligned.m16n8k16.row.col.f32.f16.f16.f32 "
        "{%0,%1,%2,%3}, {%4,%5,%6,%7}, {%8,%9}, {%0,%1,%2,%3};"
        : "+f"(d[0]), "+f"(d[1]), "+f"(d[2]), "+f"(d[3])
        : "r"(a[0]), "r"(a[1]), "r"(a[2]), "r"(a[3]), "r"(b0), "r"(b1));
}
__device__ __forceinline__ float gelu_tanh(float v) {
    float c = 0.7978845608028654f;
    return 0.5f * v * (1.0f + tanhf(c * (v + 0.044715f * v * v * v)));
}

// ---------------- tiny kernels ----------------
__global__ void clear_cnt_kernel() {
    if (threadIdx.x < NE) g_cnt[threadIdx.x] = 0;
}
__global__ void zero_out_kernel(float4* out, int n4) {
    int i = blockIdx.x * blockDim.x + threadIdx.x;
    float4 z = make_float4(0.f, 0.f, 0.f, 0.f);
    for (; i < n4; i += gridDim.x * blockDim.x) out[i] = z;
}

// ---------------- kernel: router ----------------
__global__ void router_kernel(const float* __restrict__ x, const float* __restrict__ wg) {
    int warp = (blockIdx.x * blockDim.x + threadIdx.x) >> 5;
    int lane = threadIdx.x & 31;
    if (warp >= NTOK) return;
    const float4* xr = (const float4*)(x + (size_t)warp * CDIM);

    float4 v[6];
#pragma unroll
    for (int i = 0; i < 6; i++) v[i] = xr[lane + 32 * i];

    float acc[NE];
#pragma unroll
    for (int e = 0; e < NE; e++) acc[e] = 0.0f;
#pragma unroll
    for (int i = 0; i < 6; i++) {
        int c0 = (lane + 32 * i) * 4;
        float vv[4] = {v[i].x, v[i].y, v[i].z, v[i].w};
#pragma unroll
        for (int q = 0; q < 4; q++) {
            const float4* w4 = (const float4*)(wg + (size_t)(c0 + q) * NE);
            float4 a = w4[0], b = w4[1];
            float xv = vv[q];
            acc[0] += xv * a.x; acc[1] += xv * a.y; acc[2] += xv * a.z; acc[3] += xv * a.w;
            acc[4] += xv * b.x; acc[5] += xv * b.y; acc[6] += xv * b.z; acc[7] += xv * b.w;
        }
    }
#pragma unroll
    for (int e = 0; e < NE; e++)
        for (int off = 16; off; off >>= 1)
            acc[e] += __shfl_xor_sync(0xffffffffu, acc[e], off);
    if (lane == 0) {
        int i0 = 0; float l0 = acc[0];
        for (int e = 1; e < NE; e++) if (acc[e] > l0) { l0 = acc[e]; i0 = e; }
        int i1 = -1; float l1 = -1e30f;
        for (int e = 0; e < NE; e++) if (e != i0 && acc[e] > l1) { l1 = acc[e]; i1 = e; }
        float r  = expf(l1 - l0);
        float p0 = 1.0f / (1.0f + r);
        float p1 = r / (1.0f + r);
        int pos0 = atomicAdd(&g_cnt[i0], 1);
        g_tok[i0 * NTOK + pos0] = warp; g_p[i0 * NTOK + pos0] = p0;
        int pos1 = atomicAdd(&g_cnt[i1], 1);
        g_tok[i1 * NTOK + pos1] = warp; g_p[i1 * NTOK + pos1] = p1;
    }
}

// ---------------- kernel: gather x ----------------
__global__ __launch_bounds__(256) void gather_x(const float* __restrict__ x) {
    int g = blockIdx.x * 8 + (threadIdx.x >> 5);
    int lane = threadIdx.x & 31;
    int e = g >> 11, row = g & 2047;
    int cnt = g_cnt[e];
    size_t dst = (size_t)g * CDIM;
    if (row >= cnt) {
        if (row < ((cnt + 127) & ~127)) {
            uint4 z = make_uint4(0, 0, 0, 0);
            for (int c = lane * 8; c < CDIM; c += 256)
                *(uint4*)(g_xg + dst + c) = z;
        }
        return;
    }
    int tok = g_tok[g];
    const float4* xr = (const float4*)(x + (size_t)tok * CDIM);
#pragma unroll
    for (int i = 0; i < 6; i++) {
        float4 v = xr[lane + 32 * i];
        __half2 h0 = __floats2half2_rn(v.x, v.y);
        __half2 h1 = __floats2half2_rn(v.z, v.w);
        uint2 pk = make_uint2(*(uint32_t*)&h0, *(uint32_t*)&h1);
        *(uint2*)(g_xg + dst + (lane + 32 * i) * 4) = pk;
    }
}

// ---------------- kernel: repack weights ----------------
// src[(k*NT + n)*8 + e] -> dst[(e*NT + n)*KT + k]
__global__ __launch_bounds__(256) void repack_w(const float* __restrict__ src,
                                                __half* __restrict__ dst,
                                                int KT, int NT, int yoff) {
    __shared__ __align__(16) unsigned short st[8][264];
    int n  = blockIdx.y + yoff;
    int k0 = blockIdx.x * 256;
    int t  = threadIdx.x;
    int k  = k0 + t;
    const float4* s4 = (const float4*)(src + ((size_t)k * NT + n) * 8);
    float4 a = s4[0], b = s4[1];
    float v[8] = {a.x, a.y, a.z, a.w, b.x, b.y, b.z, b.w};
#pragma unroll
    for (int e = 0; e < 8; e++)
        st[e][t] = __half_as_ushort(__float2half(v[e]));
    __syncthreads();
    int p = t >> 5, i = t & 31;
    size_t off = ((size_t)p * NT + n) * KT + k0 + i * 8;
    *(uint4*)(dst + off) = *(const uint4*)&st[p][i * 8];
}

// ---------------- tensor-core GEMM (pure fp16, cp.async pipeline, BK=32) ---
// PHASE 1: D = Xg @ Wfc^T, gelu -> g_h             (WM=4 -> BM=128)
// PHASE 2: D = H  @ Wp^T,  * p -> atomicAdd(out)   (WM=2 -> BM=64)
template <int WM, int PHASE>
__global__ __launch_bounds__(256) void gemm_ws(
    const __half* __restrict__ A, const __half* __restrict__ B,
    int Kdim, int Ndim, float* __restrict__ out) {

    constexpr int BM  = WM * 32;
    constexpr int BN  = 128;
    constexpr int BK  = 32;
    constexpr int SA  = BK + 8;
    constexpr int NST = 3;
    constexpr int ASZ = BM * SA;
    constexpr int BSZ = BN * SA;
    constexpr int STG = ASZ + BSZ;

    int e   = blockIdx.z;
    int cnt = g_cnt[e];
    int m0  = blockIdx.x * BM;
    if (m0 >= cnt) return;
    int n0  = blockIdx.y * BN;

    extern __shared__ __half sm[];
    uint32_t sbase = smem_u32(sm);

    const __half* A_p = A + ((size_t)e * NTOK + m0) * Kdim;
    const __half* B_p = B + ((size_t)e * Ndim + n0) * Kdim;

    int tid  = threadIdx.x;
    int lane = tid & 31;
    int wid  = tid >> 5;
    int wm   = wid & 1;
    int wn   = wid >> 1;
    int mb   = wm * WM * 16;
    int nb   = wn * 32;

    auto issue = [&](int stage, int kb) {
        int k0 = kb * BK;
        uint32_t s0 = sbase + stage * STG * 2;
#pragma unroll
        for (int t = tid; t < BM * 4; t += 256) {
            int r = t >> 2, c = t & 3;
            cpa16(s0 + (r * SA + c * 8) * 2, A_p + (size_t)r * Kdim + k0 + c * 8);
        }
#pragma unroll
        for (int t = tid; t < BN * 4; t += 256) {
            int r = t >> 2, c = t & 3;
            cpa16(s0 + (ASZ + r * SA + c * 8) * 2, B_p + (size_t)r * Kdim + k0 + c * 8);
        }
        CP_COMMIT();
    };

    float acc[WM][4][4];
#pragma unroll
    for (int i = 0; i < WM; i++)
#pragma unroll
        for (int j = 0; j < 4; j++)
#pragma unroll
            for (int q = 0; q < 4; q++) acc[i][j][q] = 0.0f;

    int q8   = lane >> 3;
    int rr   = lane & 7;
    int lrow = rr + (q8 & 1) * 8;
    int lcol = (q8 >> 1) * 8;

    auto compute = [&](int stage) {
        uint32_t s0 = sbase + stage * STG * 2;
#pragma unroll
        for (int kk = 0; kk < BK; kk += 16) {
            uint32_t a[WM][4];
#pragma unroll
            for (int mi = 0; mi < WM; mi++)
                ldsm4(a[mi], s0 + ((mb + mi * 16 + lrow) * SA + kk + lcol) * 2);
#pragma unroll
            for (int np = 0; np < 2; np++) {
                uint32_t b[4];
                ldsm4(b, s0 + (ASZ + (nb + np * 16 + lrow) * SA + kk + lcol) * 2);
#pragma unroll
                for (int s = 0; s < 2; s++)
#pragma unroll
                    for (int mi = 0; mi < WM; mi++)
                        mma16816(acc[mi][np * 2 + s], a[mi], b[s], b[s + 2]);
            }
        }
    };

    int KIT = Kdim / BK;
#pragma unroll
    for (int s = 0; s < NST - 1; s++) issue(s, s);
#pragma unroll 1
    for (int it = 0; it < KIT; it++) {
        CP_WAIT(NST - 2);
        __syncthreads();
        int nk = it + NST - 1;
        if (nk < KIT) issue(nk % NST, nk);
        compute(it % NST);
    }

    // ---------------- epilogue ----------------
    int fr = lane >> 2;
    int fc = (lane & 3) * 2;

    if (PHASE == 1) {
#pragma unroll
        for (int mi = 0; mi < WM; mi++) {
#pragma unroll
            for (int half = 0; half < 2; half++) {
                int r = m0 + mb + mi * 16 + fr + half * 8;
                size_t base = ((size_t)e * NTOK + r) * HDIM;
#pragma unroll
                for (int ni = 0; ni < 4; ni++) {
                    int cg = n0 + nb + ni * 8 + fc;
                    float v0 = gelu_tanh(acc[mi][ni][half * 2 + 0]);
                    float v1 = gelu_tanh(acc[mi][ni][half * 2 + 1]);
                    uint32_t pk = (uint32_t)__half_as_ushort(__float2half(v0)) |
                                  ((uint32_t)__half_as_ushort(__float2half(v1)) << 16);
                    *(uint32_t*)(g_h + base + cg) = pk;
                }
            }
        }
    } else {
#pragma unroll
        for (int mi = 0; mi < WM; mi++) {
#pragma unroll
            for (int half = 0; half < 2; half++) {
                int slot = m0 + mb + mi * 16 + fr + half * 8;
                if (slot < cnt) {
                    int   tok = g_tok[e * NTOK + slot];
                    float pw  = g_p[e * NTOK + slot];
                    float* orow = out + (size_t)tok * CDIM;
#pragma unroll
                    for (int ni = 0; ni < 4; ni++) {
                        int cg = n0 + nb + ni * 8 + fc;
                        atomicAdd(orow + cg,     pw * acc[mi][ni][half * 2 + 0]);
                        atomicAdd(orow + cg + 1, pw * acc[mi][ni][half * 2 + 1]);
                    }
                }
            }
        }
    }
}

// ---------------- host ----------------
extern "C" void kernel_launch(void* const* d_in, const int* in_sizes, int n_in,
                              void* d_out, int out_size) {
    const float* x      = (const float*)d_in[0];
    const float* w_fc   = (const float*)d_in[1];
    const float* w_proj = (const float*)d_in[2];
    const float* w_gate = (const float*)d_in[3];
    float* out = (float*)d_out;

    void *p_f, *p_p, *p_x, *p_h;
    cudaGetSymbolAddress(&p_f, g_wfc);
    cudaGetSymbolAddress(&p_p, g_wp);
    cudaGetSymbolAddress(&p_x, g_xg);
    cudaGetSymbolAddress(&p_h, g_h);

    constexpr int SMEM1 = 3 * (128 * 40 + 128 * 40) * 2;  // 61440
    constexpr int SMEM2 = 3 * (64 * 40 + 128 * 40) * 2;   // 46080

    static cudaStream_t s2 = nullptr, s3 = nullptr;
    static cudaEvent_t ev0, ev_fc0, ev_fc1, ev_pj, ev_z;
    if (!s2) {
        cudaStreamCreateWithFlags(&s2, cudaStreamNonBlocking);
        cudaStreamCreateWithFlags(&s3, cudaStreamNonBlocking);
        cudaEventCreateWithFlags(&ev0,   cudaEventDisableTiming);
        cudaEventCreateWithFlags(&ev_fc0, cudaEventDisableTiming);
        cudaEventCreateWithFlags(&ev_fc1, cudaEventDisableTiming);
        cudaEventCreateWithFlags(&ev_pj,  cudaEventDisableTiming);
        cudaEventCreateWithFlags(&ev_z,   cudaEventDisableTiming);
        cudaFuncSetAttribute(gemm_ws<4, 1>, cudaFuncAttributeMaxDynamicSharedMemorySize, SMEM1);
        cudaFuncSetAttribute(gemm_ws<2, 2>, cudaFuncAttributeMaxDynamicSharedMemorySize, SMEM2);
    }

    // fork
    cudaEventRecord(ev0, 0);
    cudaStreamWaitEvent(s2, ev0, 0);
    cudaStreamWaitEvent(s3, ev0, 0);

    // s2: repack_fc half 0, then repack_proj (hidden under gemm1)
    repack_w<<<dim3(CDIM / 256, HDIM / 2), 256, 0, s2>>>(w_fc, (__half*)p_f, CDIM, HDIM, 0);
    cudaEventRecord(ev_fc0, s2);
    // s3: repack_fc half 1, then zero_out
    repack_w<<<dim3(CDIM / 256, HDIM / 2), 256, 0, s3>>>(w_fc, (__half*)p_f, CDIM, HDIM, HDIM / 2);
    cudaEventRecord(ev_fc1, s3);

    repack_w<<<dim3(HDIM / 256, CDIM), 256, 0, s2>>>(w_proj, (__half*)p_p, HDIM, CDIM, 0);
    cudaEventRecord(ev_pj, s2);
    zero_out_kernel<<<256, 256, 0, s3>>>((float4*)out, NTOK * CDIM / 4);
    cudaEventRecord(ev_z, s3);

    // main: token path
    clear_cnt_kernel<<<1, 32>>>();
    router_kernel<<<NTOK / 8, 256>>>(x, w_gate);
    gather_x<<<NE * NTOK / 8, 256>>>(x);

    cudaStreamWaitEvent(0, ev_fc0, 0);
    cudaStreamWaitEvent(0, ev_fc1, 0);
    dim3 g1(NTOK / 128, HDIM / 128, NE);
    gemm_ws<4, 1><<<g1, 256, SMEM1>>>((const __half*)p_x, (const __half*)p_f,
                                      CDIM, HDIM, out);
    cudaStreamWaitEvent(0, ev_pj, 0);
    cudaStreamWaitEvent(0, ev_z, 0);
    dim3 g2(NTOK / 64, CDIM / 128, NE);
    gemm_ws<2, 2><<<g2, 256, SMEM2>>>((const __half*)p_h, (const __half*)p_p,
                                      HDIM, CDIM, out);
}